// round 3
// baseline (speedup 1.0000x reference)
#include <cuda_runtime.h>
#include <cstdint>

typedef unsigned long long ull;

#define BROWS 8192
#define NOUT  512
#define NKDIM 512
#define NCODE 512
#define GROUPS 4096   // in_g*out_g
#define WDIM   64     // in_mem*out_mem

// ---------------- device scratch (no allocation allowed) ----------------
__device__ float g_Weff[NKDIM * NOUT];
__device__ int   g_idx[GROUPS];
__device__ float g_mind[GROUPS];

// ---------------- packed f32x2 helpers (Blackwell FFMA2 path) ----------------
__device__ __forceinline__ ull pack2(float x, float y) {
    ull r; asm("mov.b64 %0, {%1, %2};" : "=l"(r) : "f"(x), "f"(y)); return r;
}
__device__ __forceinline__ ull ffma2(ull a, ull b, ull c) {
    ull d; asm("fma.rn.f32x2 %0, %1, %2, %3;" : "=l"(d) : "l"(a), "l"(b), "l"(c)); return d;
}

// =====================================================================
// Kernel 1: VQ quantize. 256 blocks x 512 threads, 16 rows/block.
// Thread j owns code j; computes dot(w_r, e_j) for 16 rows while streaming
// embed coalesced from L2. dist_j = ||e_j||^2 - 2 dot ; argmin over codes via
// smem + per-warp shuffle reduce. min_dist_row = ||w_r||^2 + min_j.
// =====================================================================
#define VQ_ROWS 16

__global__ __launch_bounds__(512) void vq_kernel(
    const float* __restrict__ weight,  // [4096,64] flat
    const float* __restrict__ embed)   // [64,512]
{
    __shared__ float w_s[VQ_ROWS][WDIM];
    __shared__ float wn_s[VQ_ROWS];
    __shared__ float dist_s[VQ_ROWS][NCODE];

    const int tid = threadIdx.x;
    const int r0  = blockIdx.x * VQ_ROWS;

    // load 16x64 weight rows
    for (int t = tid; t < VQ_ROWS * WDIM; t += 512)
        w_s[t / WDIM][t % WDIM] = weight[r0 * WDIM + t];
    __syncthreads();

    if (tid < VQ_ROWS) {
        float s = 0.f;
#pragma unroll
        for (int k = 0; k < WDIM; k++) { float v = w_s[tid][k]; s += v * v; }
        wn_s[tid] = s;
    }

    float acc[VQ_ROWS];
#pragma unroll
    for (int r = 0; r < VQ_ROWS; r++) acc[r] = 0.f;
    float en = 0.f;
    const int j = tid;  // code index
#pragma unroll 4
    for (int k = 0; k < WDIM; k++) {
        float e = embed[k * NCODE + j];   // coalesced, L2-resident
        en += e * e;
#pragma unroll
        for (int r = 0; r < VQ_ROWS; r++) acc[r] += w_s[r][k] * e;
    }
#pragma unroll
    for (int r = 0; r < VQ_ROWS; r++) dist_s[r][j] = en - 2.f * acc[r];
    __syncthreads();

    // 16 warps, one row each: argmin over 512 codes
    const int warp = tid >> 5, lane = tid & 31;
    float best = 3.4e38f; int bi = 0;
    for (int c = lane; c < NCODE; c += 32) {
        float v = dist_s[warp][c];
        if (v < best) { best = v; bi = c; }
    }
#pragma unroll
    for (int off = 16; off > 0; off >>= 1) {
        float ov = __shfl_down_sync(0xffffffffu, best, off);
        int   oi = __shfl_down_sync(0xffffffffu, bi,   off);
        if (ov < best) { best = ov; bi = oi; }
    }
    if (lane == 0) {
        g_idx[r0 + warp]  = bi;
        g_mind[r0 + warp] = wn_s[warp] + best;   // exact squared distance
    }
}

// =====================================================================
// Kernel 2: build effective weight W_eff[k=g*8+i][o=og*8+om]
//   = embed[(i*8+om)*512 + idx[g*64+og]]   (use_qw)   else weight[r*64+d]
// =====================================================================
__global__ __launch_bounds__(256) void build_weff(
    const float* __restrict__ embed,
    const float* __restrict__ weight,
    const int*   __restrict__ use_qw_p)
{
    const int t = blockIdx.x * 256 + threadIdx.x;   // 0..262143
    const int o = t & (NOUT - 1);
    const int k = t >> 9;
    const int g = k >> 3, i = k & 7;
    const int og = o >> 3, om = o & 7;
    const int r = g * 64 + og;
    const int d = i * 8 + om;
    const int uq = use_qw_p ? *use_qw_p : 1;
    float v;
    if (uq) v = embed[d * NCODE + g_idx[r]];
    else    v = weight[r * WDIM + d];
    g_Weff[k * NOUT + o] = v;
}

// =====================================================================
// Kernel 3: deterministic diff reduction -> d_out[B*NOUT] (if present)
// =====================================================================
__global__ __launch_bounds__(1024) void reduce_diff(
    const int* __restrict__ use_qw_p,
    float* __restrict__ out, int out_size)
{
    __shared__ float s[1024];
    float a = 0.f;
    for (int i = threadIdx.x; i < GROUPS; i += 1024) a += g_mind[i];
    s[threadIdx.x] = a;
    __syncthreads();
    for (int st = 512; st > 0; st >>= 1) {
        if (threadIdx.x < st) s[threadIdx.x] += s[threadIdx.x + st];
        __syncthreads();
    }
    if (threadIdx.x == 0 && out_size > BROWS * NOUT) {
        int uq = use_qw_p ? *use_qw_p : 1;
        out[BROWS * NOUT] = uq ? (s[0] / (float)(GROUPS * WDIM)) : 0.f;
    }
}

// =====================================================================
// Kernel 4: SGEMM  C[8192,512] = x[8192,512] @ W_eff[512,512], fp32 exact,
// packed fma.rn.f32x2 inner loop (2 FMAs/instr), 128x128x16 tiles,
// 8x8 per thread, register prefetch across K-tiles.
// =====================================================================
#define BM 128
#define BN 128
#define BK 16

__global__ __launch_bounds__(256) void sgemm_f32x2(
    const float* __restrict__ A,   // [8192, 512]
    float* __restrict__ C)         // [8192, 512]
{
    __shared__ float As[BK][BM];   // transposed A tile
    __shared__ float Bs[BK][BN];

    const int tid = threadIdx.x;
    const int m0 = blockIdx.y * BM;
    const int n0 = blockIdx.x * BN;
    const int tn = tid & 15;        // 0..15 -> col group
    const int tm = tid >> 4;        // 0..15 -> row group

    // global-load register staging (2 float4 for A, 2 for B per thread)
    float4 a_st[2], b_st[2];

    // A: f4 index f = tid + l*256 ; row = f>>2 (0..127), kc = (f&3)*4
    // B: same f ; brow = f>>5 (0..15), bcol = (f&31)*4
    const int a_row0 = tid >> 2;
    const int a_kc   = (tid & 3) * 4;
    const int b_row0 = tid >> 5;
    const int b_col  = (tid & 31) * 4;

    auto load_tile = [&](int kt) {
#pragma unroll
        for (int l = 0; l < 2; l++) {
            a_st[l] = *(const float4*)&A[(size_t)(m0 + a_row0 + l * 64) * NKDIM + kt + a_kc];
            b_st[l] = *(const float4*)&g_Weff[(size_t)(kt + b_row0 + l * 8) * NOUT + n0 + b_col];
        }
    };

    ull acc[8][4];
#pragma unroll
    for (int i = 0; i < 8; i++)
#pragma unroll
        for (int jj = 0; jj < 4; jj++) acc[i][jj] = 0ull;  // bits of {0.f,0.f}

    load_tile(0);

    for (int kt = 0; kt < NKDIM; kt += BK) {
        __syncthreads();   // prev compute done before overwriting smem
#pragma unroll
        for (int l = 0; l < 2; l++) {
            const int row = a_row0 + l * 64;
            As[a_kc + 0][row] = a_st[l].x;
            As[a_kc + 1][row] = a_st[l].y;
            As[a_kc + 2][row] = a_st[l].z;
            As[a_kc + 3][row] = a_st[l].w;
            *(float4*)&Bs[b_row0 + l * 8][b_col] = b_st[l];
        }
        __syncthreads();

        if (kt + BK < NKDIM) load_tile(kt + BK);   // overlap next loads with compute

#pragma unroll
        for (int k = 0; k < BK; k++) {
            const float4 a0 = *(const float4*)&As[k][tm * 8];
            const float4 a1 = *(const float4*)&As[k][tm * 8 + 4];
            const ulonglong2 bb0 = *(const ulonglong2*)&Bs[k][tn * 8];
            const ulonglong2 bb1 = *(const ulonglong2*)&Bs[k][tn * 8 + 4];
            const ull bp0 = bb0.x, bp1 = bb0.y, bp2 = bb1.x, bp3 = bb1.y;
            const float av[8] = {a0.x, a0.y, a0.z, a0.w, a1.x, a1.y, a1.z, a1.w};
#pragma unroll
            for (int i = 0; i < 8; i++) {
                const ull ap = pack2(av[i], av[i]);
                acc[i][0] = ffma2(ap, bp0, acc[i][0]);
                acc[i][1] = ffma2(ap, bp1, acc[i][1]);
                acc[i][2] = ffma2(ap, bp2, acc[i][2]);
                acc[i][3] = ffma2(ap, bp3, acc[i][3]);
            }
        }
    }

    // store 8x8 per thread as 2x float4 per row
#pragma unroll
    for (int i = 0; i < 8; i++) {
        union { ull u; float2 f; } p0, p1, p2, p3;
        p0.u = acc[i][0]; p1.u = acc[i][1]; p2.u = acc[i][2]; p3.u = acc[i][3];
        float* cp = C + (size_t)(m0 + tm * 8 + i) * NOUT + n0 + tn * 8;
        *(float4*)cp       = make_float4(p0.f.x, p0.f.y, p1.f.x, p1.f.y);
        *(float4*)(cp + 4) = make_float4(p2.f.x, p2.f.y, p3.f.x, p3.f.y);
    }
}

// =====================================================================
extern "C" void kernel_launch(void* const* d_in, const int* in_sizes, int n_in,
                              void* d_out, int out_size)
{
    const float* x      = (const float*)d_in[0];   // [8192, 512]
    const float* weight = (const float*)d_in[1];   // [64,64,8,8]
    const float* embed  = (const float*)d_in[2];   // [64,512]
    const int*   use_qw = (n_in >= 4) ? (const int*)d_in[3] : nullptr;
    float* out = (float*)d_out;

    vq_kernel<<<GROUPS / VQ_ROWS, 512>>>(weight, embed);
    build_weff<<<(NKDIM * NOUT) / 256, 256>>>(embed, weight, use_qw);
    reduce_diff<<<1, 1024>>>(use_qw, out, out_size);
    sgemm_f32x2<<<dim3(NOUT / BN, BROWS / BM), 256>>>(x, out);
}

// round 6
// speedup vs baseline: 1.8213x; 1.8213x over previous
#include <cuda_runtime.h>
#include <cuda_bf16.h>
#include <cstdint>

typedef unsigned long long ull;

#define BROWS 8192
#define NOUT  512
#define NKDIM 512
#define NCODE 512
#define GROUPS 4096
#define WDIM   64

#define KEFF  1536          // 3 precision segments * 512
#define GBM   128
#define GBN   128
#define GBK   32
#define KITERS (KEFF / GBK) // 48
#define ASTR  40            // padded bf16 row stride (80B -> conflict-free ldmatrix)

// ---------------- device scratch ----------------
__device__ __nv_bfloat16 g_A2[BROWS * KEFF];   // 25.2 MB
__device__ __nv_bfloat16 g_B2[NOUT * KEFF];    // 1.6 MB
__device__ int   g_idx[GROUPS];
__device__ float g_mind[GROUPS];

__device__ __forceinline__ uint32_t smem_u32(const void* p) {
    uint32_t a;
    asm("{ .reg .u64 t; cvta.to.shared.u64 t, %1; cvt.u32.u64 %0, t; }" : "=r"(a) : "l"(p));
    return a;
}
__device__ __forceinline__ void cp16(uint32_t dst, const void* src) {
    asm volatile("cp.async.cg.shared.global [%0], [%1], 16;" :: "r"(dst), "l"(src));
}
#define CP_COMMIT() asm volatile("cp.async.commit_group;" ::: "memory")
#define CP_WAIT0()  asm volatile("cp.async.wait_group 0;" ::: "memory")

__device__ __forceinline__ void ldm_x4(uint32_t addr, uint32_t& r0, uint32_t& r1,
                                       uint32_t& r2, uint32_t& r3) {
    asm volatile("ldmatrix.sync.aligned.m8n8.x4.shared.b16 {%0,%1,%2,%3}, [%4];"
                 : "=r"(r0), "=r"(r1), "=r"(r2), "=r"(r3) : "r"(addr));
}
__device__ __forceinline__ void mma_bf16(float* d, const uint32_t* a, const uint32_t* b) {
    asm volatile(
        "mma.sync.aligned.m16n8k16.row.col.f32.bf16.bf16.f32 "
        "{%0,%1,%2,%3}, {%4,%5,%6,%7}, {%8,%9}, {%0,%1,%2,%3};"
        : "+f"(d[0]), "+f"(d[1]), "+f"(d[2]), "+f"(d[3])
        : "r"(a[0]), "r"(a[1]), "r"(a[2]), "r"(a[3]), "r"(b[0]), "r"(b[1]));
}

// =====================================================================
// Kernel 1: VQ quantize (verified in R3)
// =====================================================================
#define VQ_ROWS 16

__global__ __launch_bounds__(512) void vq_kernel(
    const float* __restrict__ weight, const float* __restrict__ embed)
{
    __shared__ float w_s[VQ_ROWS][WDIM];
    __shared__ float wn_s[VQ_ROWS];
    __shared__ float dist_s[VQ_ROWS][NCODE];

    const int tid = threadIdx.x;
    const int r0  = blockIdx.x * VQ_ROWS;

    for (int t = tid; t < VQ_ROWS * WDIM; t += 512)
        w_s[t / WDIM][t % WDIM] = weight[r0 * WDIM + t];
    __syncthreads();

    if (tid < VQ_ROWS) {
        float s = 0.f;
#pragma unroll
        for (int k = 0; k < WDIM; k++) { float v = w_s[tid][k]; s += v * v; }
        wn_s[tid] = s;
    }

    float acc[VQ_ROWS];
#pragma unroll
    for (int r = 0; r < VQ_ROWS; r++) acc[r] = 0.f;
    float en = 0.f;
    const int j = tid;
#pragma unroll 4
    for (int k = 0; k < WDIM; k++) {
        float e = embed[k * NCODE + j];
        en += e * e;
#pragma unroll
        for (int r = 0; r < VQ_ROWS; r++) acc[r] += w_s[r][k] * e;
    }
#pragma unroll
    for (int r = 0; r < VQ_ROWS; r++) dist_s[r][j] = en - 2.f * acc[r];
    __syncthreads();

    const int warp = tid >> 5, lane = tid & 31;
    float best = 3.4e38f; int bi = 0;
    for (int c = lane; c < NCODE; c += 32) {
        float v = dist_s[warp][c];
        if (v < best) { best = v; bi = c; }
    }
#pragma unroll
    for (int off = 16; off > 0; off >>= 1) {
        float ov = __shfl_down_sync(0xffffffffu, best, off);
        int   oi = __shfl_down_sync(0xffffffffu, bi,   off);
        if (ov < best) { best = ov; bi = oi; }
    }
    if (lane == 0) {
        g_idx[r0 + warp]  = bi;
        g_mind[r0 + warp] = wn_s[warp] + best;
    }
}

// =====================================================================
// Kernel 2: x -> A2 bf16 row-major [8192][1536], segments [Ah | Al | Ah]
// =====================================================================
__global__ __launch_bounds__(256) void convert_a(const float* __restrict__ x)
{
    const int t = blockIdx.x * 256 + threadIdx.x;
    const int m = t >> 8;
    const int k = (t & 255) * 2;

    const float2 v = *(const float2*)&x[m * NKDIM + k];
    __nv_bfloat162 hi = __float22bfloat162_rn(v);
    float2 res = make_float2(v.x - __bfloat162float(hi.x), v.y - __bfloat162float(hi.y));
    __nv_bfloat162 lo = __float22bfloat162_rn(res);

    __nv_bfloat16* row = g_A2 + (size_t)m * KEFF;
    *(__nv_bfloat162*)&row[k]        = hi;
    *(__nv_bfloat162*)&row[512 + k]  = lo;
    *(__nv_bfloat162*)&row[1024 + k] = hi;
}

// =====================================================================
// Kernel 3: W_eff^T -> B2 bf16 row-major [512 n][1536 k], segs [Bh | Bh | Bl]
// Weff[k=g*8+i][n=og*8+om] = embed[(i*8+om)*512 + idx[g*64+og]]
// =====================================================================
__global__ __launch_bounds__(256) void convert_b(
    const float* __restrict__ embed, const float* __restrict__ weight,
    const int* __restrict__ use_qw_p)
{
    const int n = blockIdx.x;          // 0..511
    const int k = threadIdx.x * 2;     // even k
    const int g = k >> 3, i0 = k & 7;
    const int og = n >> 3, om = n & 7;
    const int uq = use_qw_p ? *use_qw_p : 1;

    float v0, v1;
    if (uq) {
        const int ix = g_idx[g * 64 + og];
        v0 = embed[(i0 * 8 + om) * NCODE + ix];
        v1 = embed[((i0 + 1) * 8 + om) * NCODE + ix];
    } else {
        v0 = weight[(g * 64 + og) * WDIM + i0 * 8 + om];
        v1 = weight[(g * 64 + og) * WDIM + (i0 + 1) * 8 + om];
    }
    __nv_bfloat162 hi = __float22bfloat162_rn(make_float2(v0, v1));
    __nv_bfloat162 lo = __float22bfloat162_rn(
        make_float2(v0 - __bfloat162float(hi.x), v1 - __bfloat162float(hi.y)));

    __nv_bfloat16* row = g_B2 + (size_t)n * KEFF;
    *(__nv_bfloat162*)&row[k]        = hi;
    *(__nv_bfloat162*)&row[512 + k]  = hi;
    *(__nv_bfloat162*)&row[1024 + k] = lo;
}

// =====================================================================
// Kernel 4: diff reduction (verified in R3)
// =====================================================================
__global__ __launch_bounds__(1024) void reduce_diff(
    const int* __restrict__ use_qw_p, float* __restrict__ out, int out_size)
{
    __shared__ float s[1024];
    float a = 0.f;
    for (int i = threadIdx.x; i < GROUPS; i += 1024) a += g_mind[i];
    s[threadIdx.x] = a;
    __syncthreads();
    for (int st = 512; st > 0; st >>= 1) {
        if (threadIdx.x < st) s[threadIdx.x] += s[threadIdx.x + st];
        __syncthreads();
    }
    if (threadIdx.x == 0 && out_size > BROWS * NOUT) {
        int uq = use_qw_p ? *use_qw_p : 1;
        out[BROWS * NOUT] = uq ? (s[0] / (float)(GROUPS * WDIM)) : 0.f;
    }
}

// =====================================================================
// Kernel 5: bf16 tensor-core GEMM (mma.sync m16n8k16, baseline PTX).
// C[8192,512] = A2[8192,1536] @ B2[512,1536]^T, fp32 accum.
// 128x128 CTA tile, 8 warps (4m x 2n), warp tile 32x64, BK=32,
// 2-stage cp.async pipeline, static smem.
// =====================================================================
__global__ __launch_bounds__(256, 2) void gemm_mma(float* __restrict__ C)
{
    __shared__ __nv_bfloat16 As[2][GBM][ASTR];  // 20 KB
    __shared__ __nv_bfloat16 Bs[2][GBN][ASTR];  // 20 KB

    const int tid  = threadIdx.x;
    const int lane = tid & 31;
    const int wid  = tid >> 5;
    const int wm   = wid & 3;    // 4 warps along M, 32 rows each
    const int wn   = wid >> 2;   // 2 warps along N, 64 cols each

    const int m0 = blockIdx.y * GBM;
    const int n0 = blockIdx.x * GBN;

    const __nv_bfloat16* Ag = g_A2 + (size_t)m0 * KEFF;
    const __nv_bfloat16* Bg = g_B2 + (size_t)n0 * KEFF;

    // cp.async indexing: 512 16B-chunks per tile, 2 per thread per matrix
    const int c0_row = tid >> 2;          // chunk row for l=0 (tid..)
    const int c0_seg = tid & 3;
    const int c1_row = (tid + 256) >> 2;
    const int c1_seg = tid & 3;           // (tid+256)&3 == tid&3

    float acc[2][8][4];
#pragma unroll
    for (int mt = 0; mt < 2; mt++)
#pragma unroll
        for (int nt = 0; nt < 8; nt++)
#pragma unroll
            for (int q = 0; q < 4; q++) acc[mt][nt][q] = 0.f;

    auto load_stage = [&](int s, int kt) {
        cp16(smem_u32(&As[s][c0_row][c0_seg * 8]), Ag + (size_t)c0_row * KEFF + kt + c0_seg * 8);
        cp16(smem_u32(&As[s][c1_row][c1_seg * 8]), Ag + (size_t)c1_row * KEFF + kt + c1_seg * 8);
        cp16(smem_u32(&Bs[s][c0_row][c0_seg * 8]), Bg + (size_t)c0_row * KEFF + kt + c0_seg * 8);
        cp16(smem_u32(&Bs[s][c1_row][c1_seg * 8]), Bg + (size_t)c1_row * KEFF + kt + c1_seg * 8);
    };

    load_stage(0, 0);
    CP_COMMIT();

    for (int it = 0; it < KITERS; it++) {
        CP_WAIT0();
        __syncthreads();
        if (it + 1 < KITERS) {
            load_stage((it + 1) & 1, (it + 1) * GBK);
            CP_COMMIT();
        }
        const int s = it & 1;

        // lane base addresses for ldmatrix
        // A frag (16x16): row = wm*32 + mt*16 + (lane&15), col = ks*16 + (lane>>4)*8
        // B frag x4 (two 8-col n-tiles): q=lane>>3, r=lane&7:
        //   n = wn*64 + np*16 + (q>>1)*8 + r ; k = ks*16 + (q&1)*8
        const uint32_t a_base = smem_u32(&As[s][0][0]);
        const uint32_t b_base = smem_u32(&Bs[s][0][0]);
        const uint32_t a_lane0 = a_base +
            ((wm * 32 + (lane & 15)) * ASTR + (lane >> 4) * 8) * 2;
        const int bq = lane >> 3, br = lane & 7;
        const uint32_t b_lane0 = b_base +
            ((wn * 64 + (bq >> 1) * 8 + br) * ASTR + (bq & 1) * 8) * 2;

#pragma unroll
        for (int ks = 0; ks < 2; ks++) {
            uint32_t a[2][4], b[8][2];
#pragma unroll
            for (int mt = 0; mt < 2; mt++)
                ldm_x4(a_lane0 + (mt * 16 * ASTR + ks * 16) * 2,
                       a[mt][0], a[mt][1], a[mt][2], a[mt][3]);
#pragma unroll
            for (int np = 0; np < 4; np++)
                ldm_x4(b_lane0 + (np * 16 * ASTR + ks * 16) * 2,
                       b[np * 2][0], b[np * 2][1], b[np * 2 + 1][0], b[np * 2 + 1][1]);
#pragma unroll
            for (int mt = 0; mt < 2; mt++)
#pragma unroll
                for (int nt = 0; nt < 8; nt++)
                    mma_bf16(acc[mt][nt], a[mt], b[nt]);
        }
    }

    // Epilogue: lane l of mma tile holds rows (l>>2), (l>>2)+8; cols (l&3)*2, +1
#pragma unroll
    for (int mt = 0; mt < 2; mt++) {
        const int r0 = m0 + wm * 32 + mt * 16 + (lane >> 2);
#pragma unroll
        for (int nt = 0; nt < 8; nt++) {
            const int c = n0 + wn * 64 + nt * 8 + (lane & 3) * 2;
            *(float2*)&C[(size_t)r0 * NOUT + c]       = make_float2(acc[mt][nt][0], acc[mt][nt][1]);
            *(float2*)&C[(size_t)(r0 + 8) * NOUT + c] = make_float2(acc[mt][nt][2], acc[mt][nt][3]);
        }
    }
}

// =====================================================================
extern "C" void kernel_launch(void* const* d_in, const int* in_sizes, int n_in,
                              void* d_out, int out_size)
{
    const float* x      = (const float*)d_in[0];   // [8192, 512]
    const float* weight = (const float*)d_in[1];   // [64,64,8,8]
    const float* embed  = (const float*)d_in[2];   // [64,512]
    const int*   use_qw = (n_in >= 4) ? (const int*)d_in[3] : nullptr;
    float* out = (float*)d_out;

    vq_kernel<<<GROUPS / VQ_ROWS, 512>>>(weight, embed);
    convert_b<<<NOUT, 256>>>(embed, weight, use_qw);
    convert_a<<<BROWS, 256>>>(x);
    reduce_diff<<<1, 1024>>>(use_qw, out, out_size);
    gemm_mma<<<dim3(NOUT / GBN, BROWS / GBM), 256>>>(out);
}